// round 14
// baseline (speedup 1.0000x reference)
#include <cuda_runtime.h>

#define BB    8
#define NMAX  128
#define HH    192
#define WW    256
#define INV_DOWN 0.125f
#define NBOX   (BB * NMAX)     // 1024 boxes
#define WPB    2               // warps (=boxes) per CTA -> finer placement
#define GRIDB  (NBOX / WPB)    // 512 CTAs
#define CMAX   13              // 13*32 = 416 >= 20*20 = 400 (max support)
#define CMID   8               // 8*32 = 256
#define CSMALL 4               // 4*32 = 128 (covers avg ~11x11 boxes)

// Antiderivative of the bilinear hat kernel, clipped to [-1, 1] (branchless)
__device__ __forceinline__ float hatP(float u) {
    u = fminf(1.0f, fmaxf(-1.0f, u));
    float neg = 0.5f * (u + 1.0f) * (u + 1.0f);
    float pos = 0.5f + u - 0.5f * u * u;
    return (u <= 0.0f) ? neg : pos;
}

// Loop-free region accumulate: NC predicated cells per lane, all loads batched.
template <int NC>
__device__ __forceinline__ float region_acc(
    int lane, int total, int nx, unsigned magic,
    int ix0, int iy0,
    float x1, float x2, float y1, float y2,
    const float* __restrict__ denB, const float* __restrict__ postN)
{
    float dv[NC], pv[NC];
    #pragma unroll
    for (int i = 0; i < NC; i++) {
        const int k  = lane + i * 32;
        const int jy = (int)__umulhi((unsigned)k, magic);
        const int jx = k - jy * nx;
        const int idx = (iy0 + jy) * WW + (ix0 + jx);
        const bool m = (k < total);
        dv[i] = m ? __ldg(denB  + idx) : 0.0f;
        pv[i] = m ? __ldg(postN + idx) : 0.0f;
    }
    float a0 = 0.0f, a1 = 0.0f;
    #pragma unroll
    for (int i = 0; i < NC; i++) {
        const int k  = lane + i * 32;
        const int jy = (int)__umulhi((unsigned)k, magic);
        const int jx = k - jy * nx;
        const float fx = (float)(ix0 + jx);
        const float fy = (float)(iy0 + jy);
        const float wxv = hatP(x2 - fx) - hatP(x1 - fx);
        const float wyv = hatP(y2 - fy) - hatP(y1 - fy);
        const float v = (wxv * wyv) * (dv[i] * pv[i]);
        if (i & 1) a1 += v; else a0 += v;
    }
    return a0 + a1;
}

__global__ __launch_bounds__(WPB * 32)
void count_kernel(const float* __restrict__ den,     // [B, 1, H, W]
                  const float* __restrict__ hboxes,  // [B, NMAX, 5]
                  const float* __restrict__ post,    // [B, NMAX, H, W]
                  float* __restrict__ out)           // zeroed by memset node
{
    const int w    = threadIdx.x >> 5;
    const int lane = threadIdx.x & 31;
    const int bn   = blockIdx.x * WPB + w;      // this warp's box
    const int b    = bn >> 7;                   // image index

    // All scalar loads issued up-front (one round-trip, MLP=9).
    const float* box = hboxes + (size_t)bn * 5;
    const float bx1 = __ldg(box + 0);
    const float by1 = __ldg(box + 1);
    const float bx2 = __ldg(box + 2);
    const float by2 = __ldg(box + 3);
    const float lab = __ldg(box + 4);

    const float* labB = hboxes + (size_t)b * NMAX * 5 + 4;   // label stride 5
    const float l0 = __ldg(labB + (lane      ) * 5);
    const float l1 = __ldg(labB + (lane + 32 ) * 5);
    const float l2 = __ldg(labB + (lane + 64 ) * 5);
    const float l3 = __ldg(labB + (lane + 96 ) * 5);

    if (lab <= 0.0f) return;        // uniform per warp; zero barriers in kernel

    const int num = __popc(__ballot_sync(0xffffffffu, l0 > 0.0f))
                  + __popc(__ballot_sync(0xffffffffu, l1 > 0.0f))
                  + __popc(__ballot_sync(0xffffffffu, l2 > 0.0f))
                  + __popc(__ballot_sync(0xffffffffu, l3 > 0.0f));   // >= 1

    const float x1 = bx1 * INV_DOWN;
    const float y1 = by1 * INV_DOWN;
    const float x2 = bx2 * INV_DOWN;
    const float y2 = by2 * INV_DOWN;

    // Tight support: weights at floor(lo)-1 and ceil(hi)+1 are exactly 0.
    const int ix0 = max(0, (int)floorf(x1));
    const int ix1 = min(WW - 1, (int)ceilf(x2));
    const int iy0 = max(0, (int)floorf(y1));
    const int iy1 = min(HH - 1, (int)ceilf(y2));
    const int nx = ix1 - ix0 + 1;   // <= 20
    const int ny = iy1 - iy0 + 1;   // <= 20
    const int total = nx * ny;      // <= 400 <= CMAX*32

    // Magic divide: jy = k / nx via umulhi, exact for k < 2^16.
    const unsigned magic =
        (unsigned)(((1ull << 32) + (unsigned)nx - 1) / (unsigned)nx);

    const float* denB  = den  + (size_t)b  * (HH * WW);
    const float* postN = post + (size_t)bn * (HH * WW);

    // Warp-uniform 3-tier dispatch; most boxes (avg ~11x11=121) take tier 4.
    float acc;
    if (total <= CSMALL * 32)
        acc = region_acc<CSMALL>(lane, total, nx, magic, ix0, iy0,
                                 x1, x2, y1, y2, denB, postN);
    else if (total <= CMID * 32)
        acc = region_acc<CMID>(lane, total, nx, magic, ix0, iy0,
                               x1, x2, y1, y2, denB, postN);
    else
        acc = region_acc<CMAX>(lane, total, nx, magic, ix0, iy0,
                               x1, x2, y1, y2, denB, postN);

    // Warp reduce, one RED per box. No smem, no bar.sync.
    #pragma unroll
    for (int o = 16; o > 0; o >>= 1)
        acc += __shfl_down_sync(0xffffffffu, acc, o);

    if (lane == 0)
        atomicAdd(out, fabsf(acc - 1.0f) * (1.0f / (float)num));
}

extern "C" void kernel_launch(void* const* d_in, const int* in_sizes, int n_in,
                              void* d_out, int out_size)
{
    // metadata order: cls(0), reg(1), off(2), den(3), fboxes(4), hboxes(5),
    //                 ctr_masks(6), post_probs(7)
    const float* den    = (const float*)d_in[3];
    const float* hboxes = (const float*)d_in[5];
    const float* post   = (const float*)d_in[7];
    float* out = (float*)d_out;

    cudaMemsetAsync(out, 0, sizeof(float));          // graph memset node
    count_kernel<<<GRIDB, WPB * 32>>>(den, hboxes, post, out);
}

// round 15
// speedup vs baseline: 1.0039x; 1.0039x over previous
#include <cuda_runtime.h>

#define BB    8
#define NMAX  128
#define HH    192
#define WW    256
#define INV_DOWN 0.125f
#define NBOX   (BB * NMAX)     // 1024 boxes
#define WPB    4               // warps (=boxes) per CTA (R13 best config)
#define GRIDB  (NBOX / WPB)    // 256 CTAs
#define CMAX   13              // 13*32 = 416 >= 20*20 = 400 (max support)
#define CSMALL 8               // fast path: 8*32 = 256

// Magic multipliers for nx = 0..20: ceil(2^32 / nx). Replaces the 64-bit
// division on the critical path between box load and region-load issue.
__constant__ unsigned c_magic[21] = {
    0u,           // nx=0 unused
    0xFFFFFFFFu,  // 1  (any value works: jy*1 recovered exactly via k - jy)
    0x80000000u,  // 2
    0x55555556u,  // 3
    0x40000000u,  // 4
    0x33333334u,  // 5
    0x2AAAAAABu,  // 6
    0x24924925u,  // 7
    0x20000000u,  // 8
    0x1C71C71Du,  // 9
    0x1999999Au,  // 10
    0x1745D175u,  // 11
    0x15555556u,  // 12
    0x13B13B14u,  // 13
    0x12492493u,  // 14
    0x11111112u,  // 15
    0x10000000u,  // 16
    0x0F0F0F10u,  // 17
    0x0E38E38Fu,  // 18
    0x0D79435Fu,  // 19
    0x0CCCCCCDu   // 20
};

// Antiderivative of the bilinear hat kernel, clipped to [-1, 1] (branchless)
__device__ __forceinline__ float hatP(float u) {
    u = fminf(1.0f, fmaxf(-1.0f, u));
    float neg = 0.5f * (u + 1.0f) * (u + 1.0f);
    float pos = 0.5f + u - 0.5f * u * u;
    return (u <= 0.0f) ? neg : pos;
}

// Fire-and-forget global reduction (no return dependency).
__device__ __forceinline__ void red_add_f32(float* addr, float v) {
    asm volatile("red.global.add.f32 [%0], %1;" :: "l"(addr), "f"(v) : "memory");
}

// Loop-free region accumulate: NC predicated cells per lane, all loads batched.
template <int NC>
__device__ __forceinline__ float region_acc(
    int lane, int total, int nx, unsigned magic,
    int ix0, int iy0,
    float x1, float x2, float y1, float y2,
    const float* __restrict__ denB, const float* __restrict__ postN)
{
    float dv[NC], pv[NC];
    #pragma unroll
    for (int i = 0; i < NC; i++) {
        const int k  = lane + i * 32;
        const int jy = (int)__umulhi((unsigned)k, magic);
        const int jx = k - jy * nx;
        const int idx = (iy0 + jy) * WW + (ix0 + jx);
        const bool m = (k < total);
        dv[i] = m ? __ldg(denB  + idx) : 0.0f;
        pv[i] = m ? __ldg(postN + idx) : 0.0f;
    }
    float a0 = 0.0f, a1 = 0.0f;
    #pragma unroll
    for (int i = 0; i < NC; i++) {
        const int k  = lane + i * 32;
        const int jy = (int)__umulhi((unsigned)k, magic);
        const int jx = k - jy * nx;
        const float fx = (float)(ix0 + jx);
        const float fy = (float)(iy0 + jy);
        const float wxv = hatP(x2 - fx) - hatP(x1 - fx);
        const float wyv = hatP(y2 - fy) - hatP(y1 - fy);
        const float v = (wxv * wyv) * (dv[i] * pv[i]);
        if (i & 1) a1 += v; else a0 += v;
    }
    return a0 + a1;
}

__global__ __launch_bounds__(WPB * 32)
void count_kernel(const float* __restrict__ den,     // [B, 1, H, W]
                  const float* __restrict__ hboxes,  // [B, NMAX, 5]
                  const float* __restrict__ post,    // [B, NMAX, H, W]
                  float* __restrict__ out)           // zeroed by memset node
{
    const int w    = threadIdx.x >> 5;
    const int lane = threadIdx.x & 31;
    const int bn   = blockIdx.x * WPB + w;      // this warp's box
    const int b    = bn >> 7;                   // image index

    // All scalar loads issued up-front (one round-trip, MLP=9).
    const float* box = hboxes + (size_t)bn * 5;
    const float bx1 = __ldg(box + 0);
    const float by1 = __ldg(box + 1);
    const float bx2 = __ldg(box + 2);
    const float by2 = __ldg(box + 3);
    const float lab = __ldg(box + 4);

    const float* labB = hboxes + (size_t)b * NMAX * 5 + 4;   // label stride 5
    const float l0 = __ldg(labB + (lane      ) * 5);
    const float l1 = __ldg(labB + (lane + 32 ) * 5);
    const float l2 = __ldg(labB + (lane + 64 ) * 5);
    const float l3 = __ldg(labB + (lane + 96 ) * 5);

    if (lab <= 0.0f) return;        // uniform per warp; zero barriers in kernel

    const int num = __popc(__ballot_sync(0xffffffffu, l0 > 0.0f))
                  + __popc(__ballot_sync(0xffffffffu, l1 > 0.0f))
                  + __popc(__ballot_sync(0xffffffffu, l2 > 0.0f))
                  + __popc(__ballot_sync(0xffffffffu, l3 > 0.0f));   // >= 1

    const float x1 = bx1 * INV_DOWN;
    const float y1 = by1 * INV_DOWN;
    const float x2 = bx2 * INV_DOWN;
    const float y2 = by2 * INV_DOWN;

    // Tight support: weights at floor(lo)-1 and ceil(hi)+1 are exactly 0.
    const int ix0 = max(0, (int)floorf(x1));
    const int ix1 = min(WW - 1, (int)ceilf(x2));
    const int iy0 = max(0, (int)floorf(y1));
    const int iy1 = min(HH - 1, (int)ceilf(y2));
    const int nx = ix1 - ix0 + 1;   // <= 20
    const int ny = iy1 - iy0 + 1;   // <= 20
    const int total = nx * ny;      // <= 400 <= CMAX*32

    // Constant-memory magic divisor (LDC ~30cyc vs ~100+cyc 64-bit division).
    const unsigned magic = c_magic[nx];

    const float* denB  = den  + (size_t)b  * (HH * WW);
    const float* postN = post + (size_t)bn * (HH * WW);

    // Warp-uniform two-tier dispatch (R13 best shape).
    float acc;
    if (total <= CSMALL * 32)
        acc = region_acc<CSMALL>(lane, total, nx, magic, ix0, iy0,
                                 x1, x2, y1, y2, denB, postN);
    else
        acc = region_acc<CMAX>(lane, total, nx, magic, ix0, iy0,
                               x1, x2, y1, y2, denB, postN);

    // Warp reduce, one fire-and-forget RED per box. No smem, no bar.sync.
    #pragma unroll
    for (int o = 16; o > 0; o >>= 1)
        acc += __shfl_down_sync(0xffffffffu, acc, o);

    if (lane == 0)
        red_add_f32(out, fabsf(acc - 1.0f) * (1.0f / (float)num));
}

extern "C" void kernel_launch(void* const* d_in, const int* in_sizes, int n_in,
                              void* d_out, int out_size)
{
    // metadata order: cls(0), reg(1), off(2), den(3), fboxes(4), hboxes(5),
    //                 ctr_masks(6), post_probs(7)
    const float* den    = (const float*)d_in[3];
    const float* hboxes = (const float*)d_in[5];
    const float* post   = (const float*)d_in[7];
    float* out = (float*)d_out;

    cudaMemsetAsync(out, 0, sizeof(float));          // graph memset node
    count_kernel<<<GRIDB, WPB * 32>>>(den, hboxes, post, out);
}

// round 16
// speedup vs baseline: 1.0118x; 1.0078x over previous
#include <cuda_runtime.h>

#define BB    8
#define NMAX  128
#define HH    192
#define WW    256
#define INV_DOWN 0.125f
#define NBOX   (BB * NMAX)     // 1024 boxes
#define WPB    4               // warps (=boxes) per CTA (best measured config)
#define GRIDB  (NBOX / WPB)    // 256 CTAs
#define CMAX   13              // 13*32 = 416 >= 20*20 = 400 (max support)
#define CSMALL 8               // fast path: 8*32 = 256

// Magic multipliers for nx = 0..20: ceil(2^32 / nx). Constant-memory lookup
// replaces a 64-bit division on the box->region critical path.
__constant__ unsigned c_magic[21] = {
    0u,
    0xFFFFFFFFu, 0x80000000u, 0x55555556u, 0x40000000u, 0x33333334u,
    0x2AAAAAABu, 0x24924925u, 0x20000000u, 0x1C71C71Du, 0x1999999Au,
    0x1745D175u, 0x15555556u, 0x13B13B14u, 0x12492493u, 0x11111112u,
    0x10000000u, 0x0F0F0F10u, 0x0E38E38Fu, 0x0D79435Fu, 0x0CCCCCCDu
};

// Antiderivative of the bilinear hat kernel, clipped to [-1, 1] (branchless)
__device__ __forceinline__ float hatP(float u) {
    u = fminf(1.0f, fmaxf(-1.0f, u));
    float neg = 0.5f * (u + 1.0f) * (u + 1.0f);
    float pos = 0.5f + u - 0.5f * u * u;
    return (u <= 0.0f) ? neg : pos;
}

// Fire-and-forget global reduction (no return dependency before exit).
__device__ __forceinline__ void red_add_f32(float* addr, float v) {
    asm volatile("red.global.add.f32 [%0], %1;" :: "l"(addr), "f"(v) : "memory");
}

// Loop-free region accumulate: NC predicated cells per lane, all loads batched.
template <int NC>
__device__ __forceinline__ float region_acc(
    int lane, int total, int nx, unsigned magic,
    int ix0, int iy0,
    float x1, float x2, float y1, float y2,
    const float* __restrict__ denB, const float* __restrict__ postN)
{
    float dv[NC], pv[NC];
    #pragma unroll
    for (int i = 0; i < NC; i++) {
        const int k  = lane + i * 32;
        const int jy = (int)__umulhi((unsigned)k, magic);
        const int jx = k - jy * nx;
        const int idx = (iy0 + jy) * WW + (ix0 + jx);
        const bool m = (k < total);
        dv[i] = m ? __ldg(denB  + idx) : 0.0f;
        pv[i] = m ? __ldg(postN + idx) : 0.0f;
    }
    float a0 = 0.0f, a1 = 0.0f;
    #pragma unroll
    for (int i = 0; i < NC; i++) {
        const int k  = lane + i * 32;
        const int jy = (int)__umulhi((unsigned)k, magic);
        const int jx = k - jy * nx;
        const float fx = (float)(ix0 + jx);
        const float fy = (float)(iy0 + jy);
        const float wxv = hatP(x2 - fx) - hatP(x1 - fx);
        const float wyv = hatP(y2 - fy) - hatP(y1 - fy);
        const float v = (wxv * wyv) * (dv[i] * pv[i]);
        if (i & 1) a1 += v; else a0 += v;
    }
    return a0 + a1;
}

__global__ __launch_bounds__(WPB * 32)
void count_kernel(const float* __restrict__ den,     // [B, 1, H, W]
                  const float* __restrict__ hboxes,  // [B, NMAX, 5]
                  const float* __restrict__ post,    // [B, NMAX, H, W]
                  float* __restrict__ out)           // zeroed by memset node
{
    const int w    = threadIdx.x >> 5;
    const int lane = threadIdx.x & 31;
    const int bn   = blockIdx.x * WPB + w;      // this warp's box
    const int b    = bn >> 7;                   // image index

    // All scalar loads issued up-front (one round-trip, MLP=9).
    const float* box = hboxes + (size_t)bn * 5;
    const float bx1 = __ldg(box + 0);
    const float by1 = __ldg(box + 1);
    const float bx2 = __ldg(box + 2);
    const float by2 = __ldg(box + 3);
    const float lab = __ldg(box + 4);

    const float* labB = hboxes + (size_t)b * NMAX * 5 + 4;   // label stride 5
    const float l0 = __ldg(labB + (lane      ) * 5);
    const float l1 = __ldg(labB + (lane + 32 ) * 5);
    const float l2 = __ldg(labB + (lane + 64 ) * 5);
    const float l3 = __ldg(labB + (lane + 96 ) * 5);

    if (lab <= 0.0f) return;        // uniform per warp; zero barriers in kernel

    const int num = __popc(__ballot_sync(0xffffffffu, l0 > 0.0f))
                  + __popc(__ballot_sync(0xffffffffu, l1 > 0.0f))
                  + __popc(__ballot_sync(0xffffffffu, l2 > 0.0f))
                  + __popc(__ballot_sync(0xffffffffu, l3 > 0.0f));   // >= 1
    // Hoisted: reciprocal overlaps the region-load latency below.
    const float invNum = 1.0f / (float)num;

    const float x1 = bx1 * INV_DOWN;
    const float y1 = by1 * INV_DOWN;
    const float x2 = bx2 * INV_DOWN;
    const float y2 = by2 * INV_DOWN;

    // Tight support: weights at floor(lo)-1 and ceil(hi)+1 are exactly 0.
    const int ix0 = max(0, (int)floorf(x1));
    const int ix1 = min(WW - 1, (int)ceilf(x2));
    const int iy0 = max(0, (int)floorf(y1));
    const int iy1 = min(HH - 1, (int)ceilf(y2));
    const int nx = ix1 - ix0 + 1;   // <= 20
    const int ny = iy1 - iy0 + 1;   // <= 20
    const int total = nx * ny;      // <= 400 <= CMAX*32

    const unsigned magic = c_magic[nx];   // LDC, ~30cyc

    const float* denB  = den  + (size_t)b  * (HH * WW);
    const float* postN = post + (size_t)bn * (HH * WW);

    // Warp-uniform two-tier dispatch.
    float acc;
    if (total <= CSMALL * 32)
        acc = region_acc<CSMALL>(lane, total, nx, magic, ix0, iy0,
                                 x1, x2, y1, y2, denB, postN);
    else
        acc = region_acc<CMAX>(lane, total, nx, magic, ix0, iy0,
                               x1, x2, y1, y2, denB, postN);

    // Butterfly reduce (all lanes converge to the same value).
    #pragma unroll
    for (int o = 16; o > 0; o >>= 1)
        acc += __shfl_xor_sync(0xffffffffu, acc, o);

    if (lane == 0)
        red_add_f32(out, fabsf(acc - 1.0f) * invNum);
}

extern "C" void kernel_launch(void* const* d_in, const int* in_sizes, int n_in,
                              void* d_out, int out_size)
{
    // metadata order: cls(0), reg(1), off(2), den(3), fboxes(4), hboxes(5),
    //                 ctr_masks(6), post_probs(7)
    const float* den    = (const float*)d_in[3];
    const float* hboxes = (const float*)d_in[5];
    const float* post   = (const float*)d_in[7];
    float* out = (float*)d_out;

    cudaMemsetAsync(out, 0, sizeof(float));          // graph memset node
    count_kernel<<<GRIDB, WPB * 32>>>(den, hboxes, post, out);
}